// round 2
// baseline (speedup 1.0000x reference)
#include <cuda_runtime.h>
#include <math.h>
#include <stdint.h>

#define NQ      16384
#define CDIM    256
#define HEADS   8
#define HD      32
#define NPTS    4
#define NLAYERS 6
#define NCAM    6
#define HF      58
#define WF      100
#define NPIX    (HF*WF)
#define NFEAT   (NCAM*NPIX)
#define FFN     512

// ---------------- scratch (static device globals; no runtime alloc) ----------
__device__ float g_q[NQ*CDIM];
__device__ float g_qp[NQ*CDIM];
__device__ float g_v[NQ*CDIM];
__device__ float g_a[NQ*CDIM];
__device__ float g_proj[NQ*CDIM];
__device__ float g_hidden[NQ*FFN];
__device__ float g_off[NQ*64];
__device__ float g_attnl[NQ*32];
__device__ float g_feats[NFEAT*CDIM];
__device__ float g_vimg[NFEAT*CDIM];
__device__ float g_refcam[NCAM*NQ*NPTS*2];
__device__ float g_valid[NCAM*NQ*NPTS];
__device__ float g_cnt[NQ];
__device__ float g_inv[NCAM*16];

// ---------------- geometry --------------------------------------------------
__global__ void k_invert(const float* __restrict__ extr) {
    int c = threadIdx.x;
    if (c >= NCAM) return;
    float a[4][8];
    for (int i = 0; i < 4; i++)
        for (int j = 0; j < 4; j++) {
            a[i][j]   = extr[c*16 + i*4 + j];
            a[i][j+4] = (i == j) ? 1.f : 0.f;
        }
    for (int col = 0; col < 4; col++) {
        int piv = col;
        for (int r = col+1; r < 4; r++)
            if (fabsf(a[r][col]) > fabsf(a[piv][col])) piv = r;
        if (piv != col)
            for (int j = 0; j < 8; j++) { float t = a[col][j]; a[col][j] = a[piv][j]; a[piv][j] = t; }
        float d = 1.f / a[col][col];
        for (int j = 0; j < 8; j++) a[col][j] *= d;
        for (int r = 0; r < 4; r++) {
            if (r == col) continue;
            float f = a[r][col];
            for (int j = 0; j < 8; j++) a[r][j] -= f * a[col][j];
        }
    }
    for (int i = 0; i < 4; i++)
        for (int j = 0; j < 4; j++)
            g_inv[c*16 + i*4 + j] = a[i][j+4];
}

__global__ void k_geom(const float* __restrict__ intr) {
    int idx = blockIdx.x * blockDim.x + threadIdx.x;
    if (idx >= NCAM*NQ*NPTS) return;
    int p = idx % NPTS;
    int n = (idx / NPTS) % NQ;
    int c = idx / (NPTS * NQ);
    float gx = ((n & 127) + 0.5f) / 128.f;
    float gy = ((n >> 7)  + 0.5f) / 128.f;
    float xm = -51.2f + gx * 102.4f;
    float ym = -51.2f + gy * 102.4f;
    float zm = -5.0f + (p + 0.5f) * 0.25f * 8.0f;
    const float* M = &g_inv[c*16];
    float px = M[0]*xm + M[1]*ym + M[2]*zm  + M[3];
    float py = M[4]*xm + M[5]*ym + M[6]*zm  + M[7];
    float pz = M[8]*xm + M[9]*ym + M[10]*zm + M[11];
    const float* I = &intr[c*9];
    float ix = I[0]*px + I[1]*py + I[2]*pz;
    float iy = I[3]*px + I[4]*py + I[5]*pz;
    float iz = I[6]*px + I[7]*py + I[8]*pz;
    float zc = fmaxf(iz, 1e-5f);
    float un = ix / (zc * WF);
    float vn = iy / (zc * HF);
    float val = (iz > 1e-5f && un >= 0.f && un <= 1.f && vn >= 0.f && vn <= 1.f) ? 1.f : 0.f;
    g_refcam[idx*2+0] = un;
    g_refcam[idx*2+1] = vn;
    g_valid[idx] = val;
}

__global__ void k_cnt() {
    int n = blockIdx.x * blockDim.x + threadIdx.x;
    if (n >= NQ) return;
    float s = 0.f;
    for (int c = 0; c < NCAM; c++)
        for (int p = 0; p < NPTS; p++)
            s += g_valid[(c*NQ + n)*NPTS + p];
    g_cnt[n] = fmaxf(s, 1.f);
}

// feats_flat[(c*NPIX+pix)*C + ch] = image_feats[c][ch][pix]   (tiled transpose)
__global__ void k_feats_t(const float* __restrict__ in) {
    __shared__ float tile[32][33];
    int pix0 = blockIdx.x * 32, ch0 = blockIdx.y * 32, c = blockIdx.z;
    int tx = threadIdx.x, ty = threadIdx.y;
    for (int i = ty; i < 32; i += 8) {
        int pix = pix0 + tx;
        tile[i][tx] = (pix < NPIX) ? in[((size_t)c*CDIM + ch0 + i)*NPIX + pix] : 0.f;
    }
    __syncthreads();
    for (int i = ty; i < 32; i += 8) {
        int pix = pix0 + i;
        if (pix < NPIX)
            g_feats[((size_t)c*NPIX + pix)*CDIM + ch0 + tx] = tile[tx][i];
    }
}

// ---------------- simple utility kernels ------------------------------------
__global__ void k_copy_in(const float* __restrict__ src) {
    int i = blockIdx.x * blockDim.x + threadIdx.x;
    if (i < NQ*CDIM) g_q[i] = src[i];
}

__global__ void k_prep_qp(const float* __restrict__ prev) {
    int i = blockIdx.x * blockDim.x + threadIdx.x;
    if (i < NQ*CDIM) g_qp[i] = 0.5f * (g_q[i] + prev[i]);
}

// ---------------- GEMM: C = A(MxK) @ B(KxN) + bias [, relu] -----------------
template<bool RELU>
__global__ void k_gemm(const float* __restrict__ A, const float* __restrict__ B,
                       const float* __restrict__ bias, float* __restrict__ Cm,
                       int M, int N, int K) {
    const int BM = 64, BN = 64, BK = 16;
    __shared__ float As[BK][BM];
    __shared__ float Bs[BK][BN];
    int tid = threadIdx.x;
    int tx = tid & 15, ty = tid >> 4;
    int m0 = blockIdx.y * BM, n0 = blockIdx.x * BN;
    float acc[4][4] = {};
    for (int k0 = 0; k0 < K; k0 += BK) {
        #pragma unroll
        for (int i = 0; i < 4; i++) {
            int idx = tid + i*256;
            int r = idx >> 4, cc = idx & 15;
            int m = m0 + r;
            As[cc][r] = (m < M) ? A[(size_t)m*K + k0 + cc] : 0.f;
        }
        #pragma unroll
        for (int i = 0; i < 4; i++) {
            int idx = tid + i*256;
            int r = idx >> 6, cc = idx & 63;
            int n = n0 + cc;
            Bs[r][cc] = (n < N) ? B[(size_t)(k0 + r)*N + n] : 0.f;
        }
        __syncthreads();
        #pragma unroll
        for (int kk = 0; kk < BK; kk++) {
            float ra[4], rb[4];
            #pragma unroll
            for (int i = 0; i < 4; i++) ra[i] = As[kk][ty*4 + i];
            #pragma unroll
            for (int j = 0; j < 4; j++) rb[j] = Bs[kk][tx*4 + j];
            #pragma unroll
            for (int i = 0; i < 4; i++)
                #pragma unroll
                for (int j = 0; j < 4; j++)
                    acc[i][j] = fmaf(ra[i], rb[j], acc[i][j]);
        }
        __syncthreads();
    }
    #pragma unroll
    for (int i = 0; i < 4; i++) {
        int m = m0 + ty*4 + i;
        if (m >= M) continue;
        #pragma unroll
        for (int j = 0; j < 4; j++) {
            int n = n0 + tx*4 + j;
            if (n >= N) continue;
            float v = acc[i][j] + bias[n];
            if (RELU) v = fmaxf(v, 0.f);
            Cm[(size_t)m*N + n] = v;
        }
    }
}

// ---------------- layernorm: out = LN(xin + add) * g + b ---------------------
__global__ void k_ln(const float* __restrict__ xin, const float* __restrict__ add,
                     const float* __restrict__ gg, const float* __restrict__ bb,
                     float* __restrict__ out) {
    int n = blockIdx.x, c = threadIdx.x;
    float x = xin[n*CDIM + c] + add[n*CDIM + c];
    __shared__ float red[8];
    __shared__ float s_mean, s_rstd;
    float s = x;
    #pragma unroll
    for (int o = 16; o > 0; o >>= 1) s += __shfl_xor_sync(0xffffffffu, s, o);
    if ((c & 31) == 0) red[c >> 5] = s;
    __syncthreads();
    if (c == 0) {
        float t = 0.f;
        #pragma unroll
        for (int i = 0; i < 8; i++) t += red[i];
        s_mean = t * (1.f / CDIM);
    }
    __syncthreads();
    float m = s_mean;
    float d = x - m;
    float sq = d * d;
    #pragma unroll
    for (int o = 16; o > 0; o >>= 1) sq += __shfl_xor_sync(0xffffffffu, sq, o);
    __syncthreads();
    if ((c & 31) == 0) red[c >> 5] = sq;
    __syncthreads();
    if (c == 0) {
        float t = 0.f;
        #pragma unroll
        for (int i = 0; i < 8; i++) t += red[i];
        s_rstd = rsqrtf(t * (1.f / CDIM) + 1e-5f);
    }
    __syncthreads();
    out[n*CDIM + c] = d * s_rstd * gg[c] + bb[c];
}

// ---------------- bilinear --------------------------------------------------
__device__ __forceinline__ float bilin(const float* __restrict__ base, int H, int W,
                                       int stride, float ix, float iy) {
    float x0f = floorf(ix), y0f = floorf(iy);
    int x0 = (int)x0f, y0 = (int)y0f;
    float fx = ix - x0f, fy = iy - y0f;
    float out = 0.f;
    #pragma unroll
    for (int dy = 0; dy < 2; dy++) {
        int yi = y0 + dy;
        if (yi < 0 || yi >= H) continue;
        float wy = dy ? fy : 1.f - fy;
        #pragma unroll
        for (int dx = 0; dx < 2; dx++) {
            int xi = x0 + dx;
            if (xi < 0 || xi >= W) continue;
            float wx = dx ? fx : 1.f - fx;
            out += wy * wx * base[((size_t)yi*W + xi) * stride];
        }
    }
    return out;
}

// ---------------- TSA deformable sampling ------------------------------------
// block = query n, warp = head h, lane = channel d
__global__ void k_tsa_sample() {
    int n = blockIdx.x;
    int h = threadIdx.x >> 5;
    int lane = threadIdx.x & 31;
    float lg0 = g_attnl[n*32 + h*4 + 0];
    float lg1 = g_attnl[n*32 + h*4 + 1];
    float lg2 = g_attnl[n*32 + h*4 + 2];
    float lg3 = g_attnl[n*32 + h*4 + 3];
    float mx = fmaxf(fmaxf(lg0, lg1), fmaxf(lg2, lg3));
    float e[4];
    e[0] = expf(lg0 - mx); e[1] = expf(lg1 - mx);
    e[2] = expf(lg2 - mx); e[3] = expf(lg3 - mx);
    float rse = 1.f / (e[0] + e[1] + e[2] + e[3]);
    float refx = ((n & 127) + 0.5f);   // already in pixel units * (1/128)*128
    float refy = ((n >> 7)  + 0.5f);
    const float* base = g_v + h*HD + lane;
    float acc = 0.f;
    #pragma unroll
    for (int p = 0; p < 4; p++) {
        float ox = g_off[n*64 + (h*4 + p)*2 + 0];
        float oy = g_off[n*64 + (h*4 + p)*2 + 1];
        float ix = refx + ox - 0.5f;   // (ref + off/128)*128 - 0.5
        float iy = refy + oy - 0.5f;
        acc += (e[p] * rse) * bilin(base, 128, 128, CDIM, ix, iy);
    }
    g_a[n*CDIM + h*HD + lane] = acc;
}

// ---------------- SCA sampling ------------------------------------------------
__global__ void k_sca_sample() {
    int n = blockIdx.x;
    int h = threadIdx.x >> 5;
    int lane = threadIdx.x & 31;
    float lg0 = g_attnl[n*32 + h*4 + 0];
    float lg1 = g_attnl[n*32 + h*4 + 1];
    float lg2 = g_attnl[n*32 + h*4 + 2];
    float lg3 = g_attnl[n*32 + h*4 + 3];
    float mx = fmaxf(fmaxf(lg0, lg1), fmaxf(lg2, lg3));
    float e[4];
    e[0] = expf(lg0 - mx); e[1] = expf(lg1 - mx);
    e[2] = expf(lg2 - mx); e[3] = expf(lg3 - mx);
    float rse = 1.f / (e[0] + e[1] + e[2] + e[3]);
    float w[4], ox[4], oy[4];
    #pragma unroll
    for (int p = 0; p < 4; p++) {
        w[p]  = e[p] * rse;
        ox[p] = g_off[n*64 + (h*4 + p)*2 + 0];
        oy[p] = g_off[n*64 + (h*4 + p)*2 + 1];
    }
    float acc = 0.f;
    for (int c = 0; c < NCAM; c++) {
        const float* rc = &g_refcam[((size_t)(c*NQ + n))*NPTS*2];
        const float* vv = &g_valid[((size_t)(c*NQ + n))*NPTS];
        const float* base = g_vimg + (size_t)c*NPIX*CDIM + h*HD + lane;
        #pragma unroll
        for (int p = 0; p < 4; p++) {
            float val = vv[p];
            if (val == 0.f) continue;
            float ix = rc[p*2+0]*WF + ox[p] - 0.5f;  // (un + ox/WF)*WF - 0.5
            float iy = rc[p*2+1]*HF + oy[p] - 0.5f;
            acc += w[p] * val * bilin(base, HF, WF, CDIM, ix, iy);
        }
    }
    g_a[n*CDIM + h*HD + lane] = acc / g_cnt[n];
}

// ---------------- output transpose q(Nq,C) -> out(C,Nq) ----------------------
__global__ void k_out_t(float* __restrict__ out) {
    __shared__ float tile[32][33];
    int n0 = blockIdx.x * 32, c0 = blockIdx.y * 32;
    int tx = threadIdx.x, ty = threadIdx.y;
    for (int i = ty; i < 32; i += 8)
        tile[i][tx] = g_q[(size_t)(n0 + i)*CDIM + c0 + tx];
    __syncthreads();
    for (int i = ty; i < 32; i += 8)
        out[(size_t)(c0 + i)*NQ + n0 + tx] = tile[tx][i];
}

// ---------------- host launch -------------------------------------------------
static void gemm(const float* A, const float* B, const float* bias, float* Cm,
                 int M, int N, int K, bool relu) {
    dim3 grid((N + 63) / 64, (M + 63) / 64);
    if (relu) k_gemm<true><<<grid, 256>>>(A, B, bias, Cm, M, N, K);
    else      k_gemm<false><<<grid, 256>>>(A, B, bias, Cm, M, N, K);
}

extern "C" void kernel_launch(void* const* d_in, const int* in_sizes, int n_in,
                              void* d_out, int out_size) {
    const float* image_feats = (const float*)d_in[0];
    const float* intr        = (const float*)d_in[1];
    const float* extr        = (const float*)d_in[2];
    const float* prev        = (const float*)d_in[3];   // (Nq,1,C) contiguous
    const float* bev         = (const float*)d_in[4];
    const float* tsa_vw = (const float*)d_in[5];
    const float* tsa_vb = (const float*)d_in[6];
    const float* tsa_ow = (const float*)d_in[7];
    const float* tsa_ob = (const float*)d_in[8];
    const float* tsa_aw = (const float*)d_in[9];
    const float* tsa_ab = (const float*)d_in[10];
    const float* tsa_pw = (const float*)d_in[11];
    const float* tsa_pb = (const float*)d_in[12];
    const float* sca_vw = (const float*)d_in[13];
    const float* sca_vb = (const float*)d_in[14];
    const float* sca_ow = (const float*)d_in[15];
    const float* sca_ob = (const float*)d_in[16];
    const float* sca_aw = (const float*)d_in[17];
    const float* sca_ab = (const float*)d_in[18];
    const float* sca_pw = (const float*)d_in[19];
    const float* sca_pb = (const float*)d_in[20];
    const float* ffn_w1 = (const float*)d_in[21];
    const float* ffn_b1 = (const float*)d_in[22];
    const float* ffn_w2 = (const float*)d_in[23];
    const float* ffn_b2 = (const float*)d_in[24];
    const float* ln1_g  = (const float*)d_in[25];
    const float* ln1_b  = (const float*)d_in[26];
    const float* ln2_g  = (const float*)d_in[27];
    const float* ln2_b  = (const float*)d_in[28];
    const float* ln3_g  = (const float*)d_in[29];
    const float* ln3_b  = (const float*)d_in[30];

    float *q_, *qp_, *v_, *a_, *proj_, *hid_, *off_, *attn_, *feats_, *vimg_;
    cudaGetSymbolAddress((void**)&q_,     g_q);
    cudaGetSymbolAddress((void**)&qp_,    g_qp);
    cudaGetSymbolAddress((void**)&v_,     g_v);
    cudaGetSymbolAddress((void**)&a_,     g_a);
    cudaGetSymbolAddress((void**)&proj_,  g_proj);
    cudaGetSymbolAddress((void**)&hid_,   g_hidden);
    cudaGetSymbolAddress((void**)&off_,   g_off);
    cudaGetSymbolAddress((void**)&attn_,  g_attnl);
    cudaGetSymbolAddress((void**)&feats_, g_feats);
    cudaGetSymbolAddress((void**)&vimg_,  g_vimg);

    // one-time geometry + feature transpose (layer-invariant)
    k_invert<<<1, NCAM>>>(extr);
    k_geom<<<(NCAM*NQ*NPTS + 255)/256, 256>>>(intr);
    k_cnt<<<(NQ + 255)/256, 256>>>();
    {
        dim3 gt((NPIX + 31)/32, CDIM/32, NCAM);
        dim3 bt(32, 8);
        k_feats_t<<<gt, bt>>>(image_feats);
    }
    k_copy_in<<<(NQ*CDIM + 255)/256, 256>>>(bev);

    for (int l = 0; l < NLAYERS; l++) {
        // ---- TSA: deform(0.5*(prev+q) @ vw + vb) -------------------------
        k_prep_qp<<<(NQ*CDIM + 255)/256, 256>>>(prev);
        gemm(qp_, tsa_vw + (size_t)l*CDIM*CDIM, tsa_vb + l*CDIM, v_, NQ, CDIM, CDIM, false);
        gemm(q_,  tsa_ow + (size_t)l*CDIM*64,   tsa_ob + l*64,   off_, NQ, 64, CDIM, false);
        gemm(q_,  tsa_aw + (size_t)l*CDIM*32,   tsa_ab + l*32,   attn_, NQ, 32, CDIM, false);
        k_tsa_sample<<<NQ, 256>>>();
        gemm(a_, tsa_pw + (size_t)l*CDIM*CDIM, tsa_pb + l*CDIM, proj_, NQ, CDIM, CDIM, false);
        k_ln<<<NQ, CDIM>>>(q_, proj_, ln1_g + l*CDIM, ln1_b + l*CDIM, q_);

        // ---- SCA ----------------------------------------------------------
        gemm(feats_, sca_vw + (size_t)l*CDIM*CDIM, sca_vb + l*CDIM, vimg_, NFEAT, CDIM, CDIM, false);
        gemm(q_, sca_ow + (size_t)l*CDIM*64, sca_ob + l*64, off_, NQ, 64, CDIM, false);
        gemm(q_, sca_aw + (size_t)l*CDIM*32, sca_ab + l*32, attn_, NQ, 32, CDIM, false);
        k_sca_sample<<<NQ, 256>>>();
        gemm(a_, sca_pw + (size_t)l*CDIM*CDIM, sca_pb + l*CDIM, proj_, NQ, CDIM, CDIM, false);
        k_ln<<<NQ, CDIM>>>(q_, proj_, ln2_g + l*CDIM, ln2_b + l*CDIM, q_);

        // ---- FFN ----------------------------------------------------------
        gemm(q_,  ffn_w1 + (size_t)l*CDIM*FFN, ffn_b1 + l*FFN, hid_, NQ, FFN, CDIM, true);
        gemm(hid_, ffn_w2 + (size_t)l*FFN*CDIM, ffn_b2 + l*CDIM, proj_, NQ, CDIM, FFN, false);
        k_ln<<<NQ, CDIM>>>(q_, proj_, ln3_g + l*CDIM, ln3_b + l*CDIM, q_);
    }

    k_out_t<<<dim3(NQ/32, CDIM/32), dim3(32, 8)>>>((float*)d_out);
}

// round 3
// speedup vs baseline: 2.0529x; 2.0529x over previous
#include <cuda_runtime.h>
#include <math.h>
#include <stdint.h>
#include <mma.h>

using namespace nvcuda;

#define NQ      16384
#define CDIM    256
#define HEADS   8
#define HD      32
#define NPTS    4
#define NLAYERS 6
#define NCAM    6
#define HF      58
#define WF      100
#define NPIX    (HF*WF)
#define NFEAT   (NCAM*NPIX)
#define FFN     512

// ---------------- scratch (static device globals; no runtime alloc) ----------
__device__ float g_q[NQ*CDIM];
__device__ float g_qp[NQ*CDIM];
__device__ float g_v[NQ*CDIM];
__device__ float g_a[NQ*CDIM];
__device__ float g_proj[NQ*CDIM];
__device__ float g_hidden[NQ*FFN];
__device__ float g_off[NQ*64];
__device__ float g_attnl[NQ*32];
__device__ float g_feats[NFEAT*CDIM];
__device__ float g_vimg[NFEAT*CDIM];
__device__ float g_refcam[NCAM*NQ*NPTS*2];
__device__ float g_valid[NCAM*NQ*NPTS];
__device__ float g_cnt[NQ];
__device__ float g_inv[NCAM*16];

// ---------------- geometry --------------------------------------------------
__global__ void k_invert(const float* __restrict__ extr) {
    int c = threadIdx.x;
    if (c >= NCAM) return;
    float a[4][8];
    for (int i = 0; i < 4; i++)
        for (int j = 0; j < 4; j++) {
            a[i][j]   = extr[c*16 + i*4 + j];
            a[i][j+4] = (i == j) ? 1.f : 0.f;
        }
    for (int col = 0; col < 4; col++) {
        int piv = col;
        for (int r = col+1; r < 4; r++)
            if (fabsf(a[r][col]) > fabsf(a[piv][col])) piv = r;
        if (piv != col)
            for (int j = 0; j < 8; j++) { float t = a[col][j]; a[col][j] = a[piv][j]; a[piv][j] = t; }
        float d = 1.f / a[col][col];
        for (int j = 0; j < 8; j++) a[col][j] *= d;
        for (int r = 0; r < 4; r++) {
            if (r == col) continue;
            float f = a[r][col];
            for (int j = 0; j < 8; j++) a[r][j] -= f * a[col][j];
        }
    }
    for (int i = 0; i < 4; i++)
        for (int j = 0; j < 4; j++)
            g_inv[c*16 + i*4 + j] = a[i][j+4];
}

__global__ void k_geom(const float* __restrict__ intr) {
    int idx = blockIdx.x * blockDim.x + threadIdx.x;
    if (idx >= NCAM*NQ*NPTS) return;
    int p = idx % NPTS;
    int n = (idx / NPTS) % NQ;
    int c = idx / (NPTS * NQ);
    float gx = ((n & 127) + 0.5f) / 128.f;
    float gy = ((n >> 7)  + 0.5f) / 128.f;
    float xm = -51.2f + gx * 102.4f;
    float ym = -51.2f + gy * 102.4f;
    float zm = -5.0f + (p + 0.5f) * 0.25f * 8.0f;
    const float* M = &g_inv[c*16];
    float px = M[0]*xm + M[1]*ym + M[2]*zm  + M[3];
    float py = M[4]*xm + M[5]*ym + M[6]*zm  + M[7];
    float pz = M[8]*xm + M[9]*ym + M[10]*zm + M[11];
    const float* I = &intr[c*9];
    float ix = I[0]*px + I[1]*py + I[2]*pz;
    float iy = I[3]*px + I[4]*py + I[5]*pz;
    float iz = I[6]*px + I[7]*py + I[8]*pz;
    float zc = fmaxf(iz, 1e-5f);
    float un = ix / (zc * WF);
    float vn = iy / (zc * HF);
    float val = (iz > 1e-5f && un >= 0.f && un <= 1.f && vn >= 0.f && vn <= 1.f) ? 1.f : 0.f;
    g_refcam[idx*2+0] = un;
    g_refcam[idx*2+1] = vn;
    g_valid[idx] = val;
}

__global__ void k_cnt() {
    int n = blockIdx.x * blockDim.x + threadIdx.x;
    if (n >= NQ) return;
    float s = 0.f;
    for (int c = 0; c < NCAM; c++)
        for (int p = 0; p < NPTS; p++)
            s += g_valid[(c*NQ + n)*NPTS + p];
    g_cnt[n] = fmaxf(s, 1.f);
}

__global__ void k_feats_t(const float* __restrict__ in) {
    __shared__ float tile[32][33];
    int pix0 = blockIdx.x * 32, ch0 = blockIdx.y * 32, c = blockIdx.z;
    int tx = threadIdx.x, ty = threadIdx.y;
    for (int i = ty; i < 32; i += 8) {
        int pix = pix0 + tx;
        tile[i][tx] = (pix < NPIX) ? in[((size_t)c*CDIM + ch0 + i)*NPIX + pix] : 0.f;
    }
    __syncthreads();
    for (int i = ty; i < 32; i += 8) {
        int pix = pix0 + i;
        if (pix < NPIX)
            g_feats[((size_t)c*NPIX + pix)*CDIM + ch0 + tx] = tile[tx][i];
    }
}

__global__ void k_copy_in(const float* __restrict__ src) {
    int i = blockIdx.x * blockDim.x + threadIdx.x;
    if (i < NQ*CDIM) g_q[i] = src[i];
}

__global__ void k_prep_qp(const float* __restrict__ prev) {
    int i = blockIdx.x * blockDim.x + threadIdx.x;
    if (i < NQ*CDIM) g_qp[i] = 0.5f * (g_q[i] + prev[i]);
}

// ---------------- tf32 WMMA GEMM: C = A(MxK) @ B(KxN) + bias [, relu] --------
// Block tile 128x64, BK=32. 8 warps, each computes 32x32 via 2x2 m16n16k8.
#define GBM 128
#define GBN 64
#define GBK 32
#define LDA 40   // BK + 8 pad
#define LDB 72   // BN + 8 pad

template<bool RELU>
__global__ __launch_bounds__(256) void k_wmma(
    const float* __restrict__ A, const float* __restrict__ B,
    const float* __restrict__ bias, float* __restrict__ Cm,
    int M, int N, int K)
{
    __shared__ __align__(16) char smem_raw[GBM*GBN*4];  // 32KB, reused as epilogue tile
    float* As = (float*)smem_raw;          // [GBM][LDA] = 128*40 = 5120 floats
    float* Bs = As + GBM*LDA;              // [GBK][LDB] = 32*72  = 2304 floats
    float* Cs = (float*)smem_raw;          // [GBM][GBN] epilogue reuse

    int tid = threadIdx.x;
    int wid = tid >> 5;
    int wr = wid >> 1;   // 0..3 (rows of 32)
    int wc = wid & 1;    // 0..1 (cols of 32)
    int m0 = blockIdx.y * GBM;
    int n0 = blockIdx.x * GBN;

    wmma::fragment<wmma::accumulator, 16, 16, 8, float> c[2][2];
    #pragma unroll
    for (int i = 0; i < 2; i++)
        #pragma unroll
        for (int j = 0; j < 2; j++)
            wmma::fill_fragment(c[i][j], 0.f);

    for (int k0 = 0; k0 < K; k0 += GBK) {
        // load A tile 128x32 (4 float4 per thread)
        {
            int col4 = tid & 7;
            int rbase = tid >> 3;
            #pragma unroll
            for (int i = 0; i < 4; i++) {
                int r = rbase + i*32;
                int m = m0 + r;
                float4 v = make_float4(0.f,0.f,0.f,0.f);
                if (m < M) v = *(const float4*)&A[(size_t)m*K + k0 + col4*4];
                v.x = wmma::__float_to_tf32(v.x);
                v.y = wmma::__float_to_tf32(v.y);
                v.z = wmma::__float_to_tf32(v.z);
                v.w = wmma::__float_to_tf32(v.w);
                *(float4*)&As[r*LDA + col4*4] = v;
            }
        }
        // load B tile 32x64 (2 float4 per thread)
        {
            int col4 = tid & 15;
            int rbase = tid >> 4;
            #pragma unroll
            for (int i = 0; i < 2; i++) {
                int r = rbase + i*16;
                int n = n0 + col4*4;
                float4 v = make_float4(0.f,0.f,0.f,0.f);
                if (n < N) v = *(const float4*)&B[(size_t)(k0 + r)*N + n];
                v.x = wmma::__float_to_tf32(v.x);
                v.y = wmma::__float_to_tf32(v.y);
                v.z = wmma::__float_to_tf32(v.z);
                v.w = wmma::__float_to_tf32(v.w);
                *(float4*)&Bs[r*LDB + col4*4] = v;
            }
        }
        __syncthreads();
        #pragma unroll
        for (int kk = 0; kk < GBK; kk += 8) {
            wmma::fragment<wmma::matrix_a, 16, 16, 8, wmma::precision::tf32, wmma::row_major> a[2];
            wmma::fragment<wmma::matrix_b, 16, 16, 8, wmma::precision::tf32, wmma::row_major> b[2];
            #pragma unroll
            for (int i = 0; i < 2; i++)
                wmma::load_matrix_sync(a[i], &As[(wr*32 + i*16)*LDA + kk], LDA);
            #pragma unroll
            for (int j = 0; j < 2; j++)
                wmma::load_matrix_sync(b[j], &Bs[kk*LDB + wc*32 + j*16], LDB);
            #pragma unroll
            for (int i = 0; i < 2; i++)
                #pragma unroll
                for (int j = 0; j < 2; j++)
                    wmma::mma_sync(c[i][j], a[i], b[j], c[i][j]);
        }
        __syncthreads();
    }

    // epilogue through smem (bias + optional relu)
    #pragma unroll
    for (int i = 0; i < 2; i++)
        #pragma unroll
        for (int j = 0; j < 2; j++)
            wmma::store_matrix_sync(&Cs[(wr*32 + i*16)*GBN + wc*32 + j*16],
                                    c[i][j], GBN, wmma::mem_row_major);
    __syncthreads();

    int col4 = tid & 15;
    int rbase = tid >> 4;
    int nn = n0 + col4*4;
    if (nn < N) {
        float4 bv = *(const float4*)&bias[nn];
        #pragma unroll
        for (int i = 0; i < 8; i++) {
            int r = rbase + i*16;
            int m = m0 + r;
            if (m >= M) continue;
            float4 v = *(float4*)&Cs[r*GBN + col4*4];
            v.x += bv.x; v.y += bv.y; v.z += bv.z; v.w += bv.w;
            if (RELU) {
                v.x = fmaxf(v.x, 0.f); v.y = fmaxf(v.y, 0.f);
                v.z = fmaxf(v.z, 0.f); v.w = fmaxf(v.w, 0.f);
            }
            *(float4*)&Cm[(size_t)m*N + nn] = v;
        }
    }
}

// ---------------- layernorm: out = LN(xin + add) * g + b ---------------------
__global__ void k_ln(const float* __restrict__ xin, const float* __restrict__ add,
                     const float* __restrict__ gg, const float* __restrict__ bb,
                     float* __restrict__ out) {
    int n = blockIdx.x, c = threadIdx.x;
    float x = xin[n*CDIM + c] + add[n*CDIM + c];
    __shared__ float red[8];
    __shared__ float s_mean, s_rstd;
    float s = x;
    #pragma unroll
    for (int o = 16; o > 0; o >>= 1) s += __shfl_xor_sync(0xffffffffu, s, o);
    if ((c & 31) == 0) red[c >> 5] = s;
    __syncthreads();
    if (c == 0) {
        float t = 0.f;
        #pragma unroll
        for (int i = 0; i < 8; i++) t += red[i];
        s_mean = t * (1.f / CDIM);
    }
    __syncthreads();
    float m = s_mean;
    float d = x - m;
    float sq = d * d;
    #pragma unroll
    for (int o = 16; o > 0; o >>= 1) sq += __shfl_xor_sync(0xffffffffu, sq, o);
    __syncthreads();
    if ((c & 31) == 0) red[c >> 5] = sq;
    __syncthreads();
    if (c == 0) {
        float t = 0.f;
        #pragma unroll
        for (int i = 0; i < 8; i++) t += red[i];
        s_rstd = rsqrtf(t * (1.f / CDIM) + 1e-5f);
    }
    __syncthreads();
    out[n*CDIM + c] = d * s_rstd * gg[c] + bb[c];
}

// ---------------- bilinear --------------------------------------------------
__device__ __forceinline__ float bilin(const float* __restrict__ base, int H, int W,
                                       int stride, float ix, float iy) {
    float x0f = floorf(ix), y0f = floorf(iy);
    int x0 = (int)x0f, y0 = (int)y0f;
    float fx = ix - x0f, fy = iy - y0f;
    float out = 0.f;
    #pragma unroll
    for (int dy = 0; dy < 2; dy++) {
        int yi = y0 + dy;
        if (yi < 0 || yi >= H) continue;
        float wy = dy ? fy : 1.f - fy;
        #pragma unroll
        for (int dx = 0; dx < 2; dx++) {
            int xi = x0 + dx;
            if (xi < 0 || xi >= W) continue;
            float wx = dx ? fx : 1.f - fx;
            out += wy * wx * base[((size_t)yi*W + xi) * stride];
        }
    }
    return out;
}

// ---------------- TSA deformable sampling ------------------------------------
__global__ void k_tsa_sample() {
    int n = blockIdx.x;
    int h = threadIdx.x >> 5;
    int lane = threadIdx.x & 31;
    float lg0 = g_attnl[n*32 + h*4 + 0];
    float lg1 = g_attnl[n*32 + h*4 + 1];
    float lg2 = g_attnl[n*32 + h*4 + 2];
    float lg3 = g_attnl[n*32 + h*4 + 3];
    float mx = fmaxf(fmaxf(lg0, lg1), fmaxf(lg2, lg3));
    float e[4];
    e[0] = expf(lg0 - mx); e[1] = expf(lg1 - mx);
    e[2] = expf(lg2 - mx); e[3] = expf(lg3 - mx);
    float rse = 1.f / (e[0] + e[1] + e[2] + e[3]);
    float refx = ((n & 127) + 0.5f);
    float refy = ((n >> 7)  + 0.5f);
    const float* base = g_v + h*HD + lane;
    float acc = 0.f;
    #pragma unroll
    for (int p = 0; p < 4; p++) {
        float ox = g_off[n*64 + (h*4 + p)*2 + 0];
        float oy = g_off[n*64 + (h*4 + p)*2 + 1];
        float ix = refx + ox - 0.5f;
        float iy = refy + oy - 0.5f;
        acc += (e[p] * rse) * bilin(base, 128, 128, CDIM, ix, iy);
    }
    g_a[n*CDIM + h*HD + lane] = acc;
}

// ---------------- SCA sampling ------------------------------------------------
__global__ void k_sca_sample() {
    int n = blockIdx.x;
    int h = threadIdx.x >> 5;
    int lane = threadIdx.x & 31;
    float lg0 = g_attnl[n*32 + h*4 + 0];
    float lg1 = g_attnl[n*32 + h*4 + 1];
    float lg2 = g_attnl[n*32 + h*4 + 2];
    float lg3 = g_attnl[n*32 + h*4 + 3];
    float mx = fmaxf(fmaxf(lg0, lg1), fmaxf(lg2, lg3));
    float e[4];
    e[0] = expf(lg0 - mx); e[1] = expf(lg1 - mx);
    e[2] = expf(lg2 - mx); e[3] = expf(lg3 - mx);
    float rse = 1.f / (e[0] + e[1] + e[2] + e[3]);
    float w[4], ox[4], oy[4];
    #pragma unroll
    for (int p = 0; p < 4; p++) {
        w[p]  = e[p] * rse;
        ox[p] = g_off[n*64 + (h*4 + p)*2 + 0];
        oy[p] = g_off[n*64 + (h*4 + p)*2 + 1];
    }
    float acc = 0.f;
    for (int c = 0; c < NCAM; c++) {
        const float* rc = &g_refcam[((size_t)(c*NQ + n))*NPTS*2];
        const float* vv = &g_valid[((size_t)(c*NQ + n))*NPTS];
        const float* base = g_vimg + (size_t)c*NPIX*CDIM + h*HD + lane;
        #pragma unroll
        for (int p = 0; p < 4; p++) {
            float val = vv[p];
            if (val == 0.f) continue;
            float ix = rc[p*2+0]*WF + ox[p] - 0.5f;
            float iy = rc[p*2+1]*HF + oy[p] - 0.5f;
            acc += w[p] * val * bilin(base, HF, WF, CDIM, ix, iy);
        }
    }
    g_a[n*CDIM + h*HD + lane] = acc / g_cnt[n];
}

// ---------------- output transpose q(Nq,C) -> out(C,Nq) ----------------------
__global__ void k_out_t(float* __restrict__ out) {
    __shared__ float tile[32][33];
    int n0 = blockIdx.x * 32, c0 = blockIdx.y * 32;
    int tx = threadIdx.x, ty = threadIdx.y;
    for (int i = ty; i < 32; i += 8)
        tile[i][tx] = g_q[(size_t)(n0 + i)*CDIM + c0 + tx];
    __syncthreads();
    for (int i = ty; i < 32; i += 8)
        out[(size_t)(c0 + i)*NQ + n0 + tx] = tile[tx][i];
}

// ---------------- host launch -------------------------------------------------
static void gemm(const float* A, const float* B, const float* bias, float* Cm,
                 int M, int N, int K, bool relu) {
    dim3 grid((N + GBN - 1) / GBN, (M + GBM - 1) / GBM);
    if (relu) k_wmma<true><<<grid, 256>>>(A, B, bias, Cm, M, N, K);
    else      k_wmma<false><<<grid, 256>>>(A, B, bias, Cm, M, N, K);
}

extern "C" void kernel_launch(void* const* d_in, const int* in_sizes, int n_in,
                              void* d_out, int out_size) {
    const float* image_feats = (const float*)d_in[0];
    const float* intr        = (const float*)d_in[1];
    const float* extr        = (const float*)d_in[2];
    const float* prev        = (const float*)d_in[3];
    const float* bev         = (const float*)d_in[4];
    const float* tsa_vw = (const float*)d_in[5];
    const float* tsa_vb = (const float*)d_in[6];
    const float* tsa_ow = (const float*)d_in[7];
    const float* tsa_ob = (const float*)d_in[8];
    const float* tsa_aw = (const float*)d_in[9];
    const float* tsa_ab = (const float*)d_in[10];
    const float* tsa_pw = (const float*)d_in[11];
    const float* tsa_pb = (const float*)d_in[12];
    const float* sca_vw = (const float*)d_in[13];
    const float* sca_vb = (const float*)d_in[14];
    const float* sca_ow = (const float*)d_in[15];
    const float* sca_ob = (const float*)d_in[16];
    const float* sca_aw = (const float*)d_in[17];
    const float* sca_ab = (const float*)d_in[18];
    const float* sca_pw = (const float*)d_in[19];
    const float* sca_pb = (const float*)d_in[20];
    const float* ffn_w1 = (const float*)d_in[21];
    const float* ffn_b1 = (const float*)d_in[22];
    const float* ffn_w2 = (const float*)d_in[23];
    const float* ffn_b2 = (const float*)d_in[24];
    const float* ln1_g  = (const float*)d_in[25];
    const float* ln1_b  = (const float*)d_in[26];
    const float* ln2_g  = (const float*)d_in[27];
    const float* ln2_b  = (const float*)d_in[28];
    const float* ln3_g  = (const float*)d_in[29];
    const float* ln3_b  = (const float*)d_in[30];

    float *q_, *qp_, *v_, *a_, *proj_, *hid_, *off_, *attn_, *feats_, *vimg_;
    cudaGetSymbolAddress((void**)&q_,     g_q);
    cudaGetSymbolAddress((void**)&qp_,    g_qp);
    cudaGetSymbolAddress((void**)&v_,     g_v);
    cudaGetSymbolAddress((void**)&a_,     g_a);
    cudaGetSymbolAddress((void**)&proj_,  g_proj);
    cudaGetSymbolAddress((void**)&hid_,   g_hidden);
    cudaGetSymbolAddress((void**)&off_,   g_off);
    cudaGetSymbolAddress((void**)&attn_,  g_attnl);
    cudaGetSymbolAddress((void**)&feats_, g_feats);
    cudaGetSymbolAddress((void**)&vimg_,  g_vimg);

    k_invert<<<1, NCAM>>>(extr);
    k_geom<<<(NCAM*NQ*NPTS + 255)/256, 256>>>(intr);
    k_cnt<<<(NQ + 255)/256, 256>>>();
    {
        dim3 gt((NPIX + 31)/32, CDIM/32, NCAM);
        dim3 bt(32, 8);
        k_feats_t<<<gt, bt>>>(image_feats);
    }
    k_copy_in<<<(NQ*CDIM + 255)/256, 256>>>(bev);

    for (int l = 0; l < NLAYERS; l++) {
        // ---- TSA ----
        k_prep_qp<<<(NQ*CDIM + 255)/256, 256>>>(prev);
        gemm(qp_, tsa_vw + (size_t)l*CDIM*CDIM, tsa_vb + l*CDIM, v_, NQ, CDIM, CDIM, false);
        gemm(q_,  tsa_ow + (size_t)l*CDIM*64,   tsa_ob + l*64,   off_, NQ, 64, CDIM, false);
        gemm(q_,  tsa_aw + (size_t)l*CDIM*32,   tsa_ab + l*32,   attn_, NQ, 32, CDIM, false);
        k_tsa_sample<<<NQ, 256>>>();
        gemm(a_, tsa_pw + (size_t)l*CDIM*CDIM, tsa_pb + l*CDIM, proj_, NQ, CDIM, CDIM, false);
        k_ln<<<NQ, CDIM>>>(q_, proj_, ln1_g + l*CDIM, ln1_b + l*CDIM, q_);

        // ---- SCA ----
        gemm(feats_, sca_vw + (size_t)l*CDIM*CDIM, sca_vb + l*CDIM, vimg_, NFEAT, CDIM, CDIM, false);
        gemm(q_, sca_ow + (size_t)l*CDIM*64, sca_ob + l*64, off_, NQ, 64, CDIM, false);
        gemm(q_, sca_aw + (size_t)l*CDIM*32, sca_ab + l*32, attn_, NQ, 32, CDIM, false);
        k_sca_sample<<<NQ, 256>>>();
        gemm(a_, sca_pw + (size_t)l*CDIM*CDIM, sca_pb + l*CDIM, proj_, NQ, CDIM, CDIM, false);
        k_ln<<<NQ, CDIM>>>(q_, proj_, ln2_g + l*CDIM, ln2_b + l*CDIM, q_);

        // ---- FFN ----
        gemm(q_,  ffn_w1 + (size_t)l*CDIM*FFN, ffn_b1 + l*FFN, hid_, NQ, FFN, CDIM, true);
        gemm(hid_, ffn_w2 + (size_t)l*FFN*CDIM, ffn_b2 + l*CDIM, proj_, NQ, CDIM, FFN, false);
        k_ln<<<NQ, CDIM>>>(q_, proj_, ln3_g + l*CDIM, ln3_b + l*CDIM, q_);
    }

    k_out_t<<<dim3(NQ/32, CDIM/32), dim3(32, 8)>>>((float*)d_out);
}